// round 2
// baseline (speedup 1.0000x reference)
#include <cuda_runtime.h>

#define FEAT 39
#define HID 1024
#define SEQ 254
#define NCLS 10
#define FC1N 100
#define BATCH 128

// Scratch (device globals; no allocation allowed in kernel_launch).
// g_seq holds xproj[s][b][h] first, overwritten in-place with h_s during the scan.
__device__ float g_seq[SEQ * BATCH * HID];    // 133 MB
__device__ float g_part[SEQ * BATCH * FC1N];  // 13 MB split-K partials for FC1
__device__ float g_h1[BATCH * FC1N];

// ---------------- packed f32x2 helpers (Blackwell) ----------------
__device__ __forceinline__ unsigned smem_u32(const void* p) {
    return (unsigned)__cvta_generic_to_shared(p);
}
__device__ __forceinline__ unsigned long long pack2(float lo, float hi) {
    unsigned long long r;
    asm("mov.b64 %0, {%1, %2};" : "=l"(r) : "f"(lo), "f"(hi));
    return r;
}
__device__ __forceinline__ void unpack2(unsigned long long v, float& lo, float& hi) {
    asm("mov.b64 {%0, %1}, %2;" : "=f"(lo), "=f"(hi) : "l"(v));
}
__device__ __forceinline__ void fma2(unsigned long long& d, unsigned long long a,
                                     unsigned long long b) {
    asm("fma.rn.f32x2 %0, %1, %2, %0;" : "+l"(d) : "l"(a), "l"(b));
}
__device__ __forceinline__ unsigned long long lds64(unsigned addr) {
    unsigned long long r;
    asm volatile("ld.shared.b64 %0, [%1];" : "=l"(r) : "r"(addr));
    return r;
}

// ---------------- kernel 1: xproj = x @ W_ih^T + b_ih + b_hh, time-major ----------------
// g_seq[(s*B+b)*HID + h] = sum_f x[b][s][f]*W_ih[h][f] + b_ih[h] + b_hh[h]
#define XP_BM 64
#define XP_BN 64
#define XP_PAD 41
__global__ __launch_bounds__(256) void xproj_kernel(
    const float* __restrict__ x, const float* __restrict__ Wih,
    const float* __restrict__ bih, const float* __restrict__ bhh) {
    __shared__ float Xs[XP_BM][XP_PAD];
    __shared__ float Ws[XP_BN][XP_PAD];
    int t = threadIdx.x;
    int n0 = blockIdx.x * XP_BN;
    int r0 = blockIdx.y * XP_BM;

    for (int i = t; i < XP_BM * FEAT; i += 256) {
        int row = i / FEAT, col = i % FEAT;
        int r = r0 + row;
        int b = r & (BATCH - 1), s = r >> 7;  // r = s*128 + b
        Xs[row][col] = x[((size_t)b * SEQ + s) * FEAT + col];
    }
    for (int i = t; i < XP_BN * FEAT; i += 256) {
        int row = i / FEAT, col = i % FEAT;
        Ws[row][col] = Wih[(size_t)(n0 + row) * FEAT + col];
    }
    __syncthreads();

    int tn = t & 15, tm = t >> 4;
    float acc[4][4] = {};
#pragma unroll
    for (int k = 0; k < FEAT; k++) {
        float a[4], w[4];
#pragma unroll
        for (int i = 0; i < 4; i++) a[i] = Xs[tm * 4 + i][k];
#pragma unroll
        for (int j = 0; j < 4; j++) w[j] = Ws[tn * 4 + j][k];
#pragma unroll
        for (int i = 0; i < 4; i++)
#pragma unroll
            for (int j = 0; j < 4; j++) acc[i][j] += a[i] * w[j];
    }
#pragma unroll
    for (int j = 0; j < 4; j++) {
        int n = n0 + tn * 4 + j;
        float bias = bih[n] + bhh[n];
#pragma unroll
        for (int i = 0; i < 4; i++) {
            int r = r0 + tm * 4 + i;
            g_seq[(size_t)r * HID + n] = acc[i][j] + bias;
        }
    }
}

// ---------------- kernel 2: one recurrence step ----------------
// out[b][j] = tanh(xp[b][j] + sum_i H[b][i] * Whh[j][i]);  xp in-place in g_seq[s]
#define ST_BM 32
#define ST_BN 32
#define ST_BK 64
#define ST_PA 34
#define ST_PB 65
__global__ __launch_bounds__(128) void step_kernel(
    int s, const float* __restrict__ h0, const float* __restrict__ Whh) {
    __shared__ float As[ST_BK][ST_PA];  // [k][m] transposed
    __shared__ float Bs[ST_BN][ST_PB];  // [j][k] natural

    const float* Hp = (s == 0) ? h0 : (g_seq + (size_t)(s - 1) * BATCH * HID);
    float* out = g_seq + (size_t)s * BATCH * HID;

    int t = threadIdx.x;
    int n0 = blockIdx.x * ST_BN;
    int m0 = blockIdx.y * ST_BM;
    int tn = t & 15, tm = t >> 4;  // tn: n-pair 0..15, tm: m-quad 0..7

    unsigned long long c00 = 0, c01 = 0, c10 = 0, c11 = 0;
    unsigned aBase = smem_u32(&As[0][0]);

    int row = (t >> 4), c4 = (t & 15);  // per-q decomposition below
    float4 va[4], vb[4];
    // prologue prefetch of tile 0
#pragma unroll
    for (int q = 0; q < 4; q++) {
        int f4 = t + q * 128;
        int r = f4 >> 4, c = f4 & 15;
        va[q] = *(const float4*)(Hp + (size_t)(m0 + r) * HID + c * 4);
        vb[q] = *(const float4*)(Whh + (size_t)(n0 + r) * HID + c * 4);
    }
    (void)row; (void)c4;

    for (int k0 = 0; k0 < HID; k0 += ST_BK) {
        // store prefetched tile to smem
#pragma unroll
        for (int q = 0; q < 4; q++) {
            int f4 = t + q * 128;
            int r = f4 >> 4, c = f4 & 15;
            As[c * 4 + 0][r] = va[q].x;
            As[c * 4 + 1][r] = va[q].y;
            As[c * 4 + 2][r] = va[q].z;
            As[c * 4 + 3][r] = va[q].w;
            Bs[r][c * 4 + 0] = vb[q].x;
            Bs[r][c * 4 + 1] = vb[q].y;
            Bs[r][c * 4 + 2] = vb[q].z;
            Bs[r][c * 4 + 3] = vb[q].w;
        }
        __syncthreads();
        // prefetch next tile (hide LDG latency under compute)
        int kn = k0 + ST_BK;
        if (kn < HID) {
#pragma unroll
            for (int q = 0; q < 4; q++) {
                int f4 = t + q * 128;
                int r = f4 >> 4, c = f4 & 15;
                va[q] = *(const float4*)(Hp + (size_t)(m0 + r) * HID + kn + c * 4);
                vb[q] = *(const float4*)(Whh + (size_t)(n0 + r) * HID + kn + c * 4);
            }
        }
#pragma unroll
        for (int k = 0; k < ST_BK; k++) {
            unsigned addr = aBase + (unsigned)((k * ST_PA + tm * 4) * 4);
            unsigned long long a0 = lds64(addr);      // (m0..m1)
            unsigned long long a1 = lds64(addr + 8);  // (m2..m3)
            float b0 = Bs[2 * tn][k], b1 = Bs[2 * tn + 1][k];
            unsigned long long bb0 = pack2(b0, b0);
            unsigned long long bb1 = pack2(b1, b1);
            fma2(c00, a0, bb0);
            fma2(c01, a0, bb1);
            fma2(c10, a1, bb0);
            fma2(c11, a1, bb1);
        }
        __syncthreads();
    }

    float r_[4][2];
    unpack2(c00, r_[0][0], r_[1][0]);
    unpack2(c01, r_[0][1], r_[1][1]);
    unpack2(c10, r_[2][0], r_[3][0]);
    unpack2(c11, r_[2][1], r_[3][1]);
#pragma unroll
    for (int i = 0; i < 4; i++) {
        int m = m0 + tm * 4 + i;
#pragma unroll
        for (int j = 0; j < 2; j++) {
            int n = n0 + 2 * tn + j;
            float xp = out[(size_t)m * HID + n];
            out[(size_t)m * HID + n] = tanhf(xp + r_[i][j]);
        }
    }
}

// ---------------- kernel 3: FC1 split-K partials (one block per timestep) ----------------
// g_part[s][b][f] = sum_{k<1024} outs[s][b][k] * W1[f][s*1024+k]
#define F1_BK 32
__global__ __launch_bounds__(256) void fc1_kernel(const float* __restrict__ W1) {
    __shared__ float Hs[BATCH][33];
    __shared__ float Ws[FC1N][33];
    int s = blockIdx.x;
    int t = threadIdx.x;
    const float* src = g_seq + (size_t)s * BATCH * HID;
    int tb = t & 63, tf = t >> 6;  // tb: b-pair 0..63, tf: f-group 0..3 (25 f each)

    float acc0[25] = {}, acc1[25] = {};
    for (int k0 = 0; k0 < HID; k0 += F1_BK) {
#pragma unroll
        for (int q = 0; q < 4; q++) {
            int f4 = t + q * 256;  // 0..1023 -> 128 rows x 8 float4
            int row = f4 >> 3, c4 = f4 & 7;
            float4 v = *(const float4*)(src + (size_t)row * HID + k0 + c4 * 4);
            Hs[row][c4 * 4 + 0] = v.x;
            Hs[row][c4 * 4 + 1] = v.y;
            Hs[row][c4 * 4 + 2] = v.z;
            Hs[row][c4 * 4 + 3] = v.w;
        }
        for (int f4 = t; f4 < FC1N * 8; f4 += 256) {
            int row = f4 >> 3, c4 = f4 & 7;
            float4 v = *(const float4*)(W1 + (size_t)row * (SEQ * HID) + (size_t)s * HID +
                                        k0 + c4 * 4);
            Ws[row][c4 * 4 + 0] = v.x;
            Ws[row][c4 * 4 + 1] = v.y;
            Ws[row][c4 * 4 + 2] = v.z;
            Ws[row][c4 * 4 + 3] = v.w;
        }
        __syncthreads();
#pragma unroll 2
        for (int k = 0; k < F1_BK; k++) {
            float a0 = Hs[2 * tb][k], a1 = Hs[2 * tb + 1][k];
#pragma unroll
            for (int j = 0; j < 25; j++) {
                float wv = Ws[tf * 25 + j][k];
                acc0[j] += a0 * wv;
                acc1[j] += a1 * wv;
            }
        }
        __syncthreads();
    }
    float* dst = g_part + (size_t)s * BATCH * FC1N;
#pragma unroll
    for (int j = 0; j < 25; j++) {
        dst[(size_t)(2 * tb) * FC1N + tf * 25 + j] = acc0[j];
        dst[(size_t)(2 * tb + 1) * FC1N + tf * 25 + j] = acc1[j];
    }
}

// ---------------- kernel 4: deterministic reduce over s + bias + relu ----------------
__global__ __launch_bounds__(256) void reduce_kernel(const float* __restrict__ b1) {
    int i = blockIdx.x * 256 + threadIdx.x;
    if (i >= BATCH * FC1N) return;
    int f = i % FC1N;
    float sum = b1[f];
    for (int s = 0; s < SEQ; s++) sum += g_part[(size_t)s * BATCH * FC1N + i];
    g_h1[i] = fmaxf(sum, 0.0f);
}

// ---------------- kernel 5: FC2 + log_softmax ----------------
__global__ __launch_bounds__(128) void fc2_kernel(const float* __restrict__ W2,
                                                  const float* __restrict__ b2,
                                                  float* __restrict__ out) {
    __shared__ float sW2[NCLS * FC1N];
    int t = threadIdx.x;  // one thread per batch row
    for (int i = t; i < NCLS * FC1N; i += 128) sW2[i] = W2[i];
    __syncthreads();

    float hv[FC1N];
#pragma unroll
    for (int f = 0; f < FC1N; f++) hv[f] = g_h1[(size_t)t * FC1N + f];

    float logits[NCLS];
#pragma unroll
    for (int c = 0; c < NCLS; c++) {
        float acc = b2[c];
#pragma unroll
        for (int f = 0; f < FC1N; f++) acc += hv[f] * sW2[c * FC1N + f];
        logits[c] = acc;
    }
    float m = logits[0];
#pragma unroll
    for (int c = 1; c < NCLS; c++) m = fmaxf(m, logits[c]);
    float sum = 0.0f;
#pragma unroll
    for (int c = 0; c < NCLS; c++) sum += expf(logits[c] - m);
    float lse = m + logf(sum);
#pragma unroll
    for (int c = 0; c < NCLS; c++) out[(size_t)t * NCLS + c] = logits[c] - lse;
}

// ---------------- launch ----------------
extern "C" void kernel_launch(void* const* d_in, const int* in_sizes, int n_in,
                              void* d_out, int out_size) {
    const float* x = (const float*)d_in[0];
    const float* h0 = (const float*)d_in[1];
    const float* Wih = (const float*)d_in[2];
    const float* Whh = (const float*)d_in[3];
    const float* bih = (const float*)d_in[4];
    const float* bhh = (const float*)d_in[5];
    const float* W1 = (const float*)d_in[6];
    const float* b1 = (const float*)d_in[7];
    const float* W2 = (const float*)d_in[8];
    const float* b2 = (const float*)d_in[9];
    float* out = (float*)d_out;
    (void)in_sizes; (void)n_in; (void)out_size;

    xproj_kernel<<<dim3(HID / XP_BN, (SEQ * BATCH) / XP_BM), 256>>>(x, Wih, bih, bhh);
    for (int s = 0; s < SEQ; s++)
        step_kernel<<<dim3(HID / ST_BN, BATCH / ST_BM), 128>>>(s, h0, Whh);
    fc1_kernel<<<SEQ, 256>>>(W1);
    reduce_kernel<<<(BATCH * FC1N + 255) / 256, 256>>>(b1);
    fc2_kernel<<<1, 128>>>(W2, b2, out);
}

// round 3
// speedup vs baseline: 2.0324x; 2.0324x over previous
#include <cuda_runtime.h>

#define FEAT 39
#define HID 1024
#define SEQ 254
#define NCLS 10
#define FC1N 100
#define BATCH 128

// Scratch (device globals; no allocation allowed).
__device__ float g_seq[SEQ * BATCH * HID];    // xproj then h_s, in place
__device__ float g_part[SEQ * BATCH * FC1N];  // FC1 split-K partials
__device__ float g_h1[BATCH * FC1N];

// ---------------- packed f32x2 + smem helpers ----------------
__device__ __forceinline__ unsigned smem_u32(const void* p) {
    return (unsigned)__cvta_generic_to_shared(p);
}
__device__ __forceinline__ void unpack2(unsigned long long v, float& lo, float& hi) {
    asm("mov.b64 {%0, %1}, %2;" : "=f"(lo), "=f"(hi) : "l"(v));
}
__device__ __forceinline__ void fma2(unsigned long long& d, unsigned long long a,
                                     unsigned long long b) {
    asm("fma.rn.f32x2 %0, %1, %2, %0;" : "+l"(d) : "l"(a), "l"(b));
}
__device__ __forceinline__ unsigned long long lds64(unsigned addr) {
    unsigned long long r;
    asm volatile("ld.shared.b64 %0, [%1];" : "=l"(r) : "r"(addr));
    return r;
}
__device__ __forceinline__ void cpasync16(unsigned dst, const void* src) {
    asm volatile("cp.async.cg.shared.global [%0], [%1], 16;" ::"r"(dst), "l"(src));
}
__device__ __forceinline__ void cp_commit() {
    asm volatile("cp.async.commit_group;");
}
template <int N>
__device__ __forceinline__ void cp_wait() {
    asm volatile("cp.async.wait_group %0;" ::"n"(N));
}

// ---------------- kernel 1: xproj = x @ W_ih^T + b_ih + b_hh, time-major ----------------
#define XP_BM 64
#define XP_BN 64
#define XP_PAD 41
__global__ __launch_bounds__(256) void xproj_kernel(
    const float* __restrict__ x, const float* __restrict__ Wih,
    const float* __restrict__ bih, const float* __restrict__ bhh) {
    __shared__ float Xs[XP_BM][XP_PAD];
    __shared__ float Ws[XP_BN][XP_PAD];
    int t = threadIdx.x;
    int n0 = blockIdx.x * XP_BN;
    int r0 = blockIdx.y * XP_BM;

    for (int i = t; i < XP_BM * FEAT; i += 256) {
        int row = i / FEAT, col = i % FEAT;
        int r = r0 + row;
        int b = r & (BATCH - 1), s = r >> 7;
        Xs[row][col] = x[((size_t)b * SEQ + s) * FEAT + col];
    }
    for (int i = t; i < XP_BN * FEAT; i += 256) {
        int row = i / FEAT, col = i % FEAT;
        Ws[row][col] = Wih[(size_t)(n0 + row) * FEAT + col];
    }
    __syncthreads();

    int tn = t & 15, tm = t >> 4;
    float acc[4][4] = {};
#pragma unroll
    for (int k = 0; k < FEAT; k++) {
        float a[4], w[4];
#pragma unroll
        for (int i = 0; i < 4; i++) a[i] = Xs[tm * 4 + i][k];
#pragma unroll
        for (int j = 0; j < 4; j++) w[j] = Ws[tn * 4 + j][k];
#pragma unroll
        for (int i = 0; i < 4; i++)
#pragma unroll
            for (int j = 0; j < 4; j++) acc[i][j] += a[i] * w[j];
    }
#pragma unroll
    for (int j = 0; j < 4; j++) {
        int n = n0 + tn * 4 + j;
        float bias = bih[n] + bhh[n];
#pragma unroll
        for (int i = 0; i < 4; i++) {
            int r = r0 + tm * 4 + i;
            g_seq[(size_t)r * HID + n] = acc[i][j] + bias;
        }
    }
}

// ---------------- kernel 2: one recurrence step (fma2-roofline design) ----------------
// out[m][n] = tanh(xp[m][n] + sum_k H[m][k] * Whh[n][k])
// 128 blocks (4 mgrp x 32 ngrp), 256 threads (8 warps).
// Warp kg owns k-slice [kg*32, kg*32+32) within each 256-k chunk; partials
// over warps are reduced through smem at the end.
// Accumulators are packed over (k even, k odd): both a and w are natural 64-bit
// smem loads -> no packing movs, no transpose, fma2-pipe-bound inner loop.
#define SPAD 260              // floats per smem row (float4-aligned, bank-spread)
#define SBUF (32 * SPAD)      // floats per (buffer, array)
#define ST_SMEM (4 * SBUF * 4)  // As[2] + Ws[2], bytes = 133120

__global__ __launch_bounds__(256) void step_kernel(
    int s, const float* __restrict__ h0, const float* __restrict__ Whh) {
    extern __shared__ float sm[];
    // As buffers: sm[0..2*SBUF), Ws buffers: sm[2*SBUF..4*SBUF)
    const float* Hp = (s == 0) ? h0 : (g_seq + (size_t)(s - 1) * BATCH * HID);
    float* out = g_seq + (size_t)s * BATCH * HID;

    int t = threadIdx.x;
    int n0 = blockIdx.x * 32;
    int m0 = blockIdx.y * 32;
    int kg = t >> 5;          // warp id = k-group
    int lane = t & 31;
    int thrm = lane >> 2;     // 0..7
    int thrn = lane & 3;      // 0..3

    unsigned smBase = smem_u32(sm);

    // staging mapping: thread t -> row = t>>3 (0..31), c4 = t&7; 8 float4 per array
    int srow = t >> 3, sc4 = t & 7;
    const float* aRow = Hp + (size_t)(m0 + srow) * HID;
    const float* wRow = Whh + (size_t)(n0 + srow) * HID;
    unsigned aDstRow = smBase + (unsigned)(srow * SPAD) * 4u;
    unsigned wDstRow = smBase + (unsigned)(2 * SBUF + srow * SPAD) * 4u;

    auto stage = [&](int chunk, int buf) {
        unsigned boff = (unsigned)(buf * SBUF) * 4u;
        int kbase = chunk * 256;
#pragma unroll
        for (int q = 0; q < 8; q++) {
            int col = (sc4 + q * 8) * 4;  // 0..252 step
            cpasync16(aDstRow + boff + (unsigned)col * 4u, aRow + kbase + col);
            cpasync16(wDstRow + boff + (unsigned)col * 4u, wRow + kbase + col);
        }
        cp_commit();
    };

    unsigned long long acc[4][8];
#pragma unroll
    for (int i = 0; i < 4; i++)
#pragma unroll
        for (int j = 0; j < 8; j++) acc[i][j] = 0ull;

    unsigned aOff[4], wOff[8];
#pragma unroll
    for (int i = 0; i < 4; i++) aOff[i] = (unsigned)((thrm + 8 * i) * SPAD) * 4u;
#pragma unroll
    for (int j = 0; j < 8; j++)
        wOff[j] = (unsigned)(2 * SBUF + (thrn + 4 * j) * SPAD) * 4u;

    auto compute = [&](int buf) {
        unsigned bOff = smBase + (unsigned)(buf * SBUF) * 4u;
        int kbase = kg * 32;
#pragma unroll
        for (int kp = 0; kp < 16; kp++) {
            unsigned kOff = (unsigned)(kbase + 2 * kp) * 4u;
            unsigned long long a[4], w[8];
#pragma unroll
            for (int i = 0; i < 4; i++) a[i] = lds64(bOff + aOff[i] + kOff);
#pragma unroll
            for (int j = 0; j < 8; j++) w[j] = lds64(bOff + wOff[j] + kOff);
#pragma unroll
            for (int i = 0; i < 4; i++)
#pragma unroll
                for (int j = 0; j < 8; j++) fma2(acc[i][j], a[i], w[j]);
        }
    };

    // software pipeline: 4 chunks, 2 buffers
    stage(0, 0);
    stage(1, 1);
    cp_wait<1>();
    __syncthreads();
    compute(0);
    __syncthreads();
    stage(2, 0);
    cp_wait<1>();
    __syncthreads();
    compute(1);
    __syncthreads();
    stage(3, 1);
    cp_wait<1>();
    __syncthreads();
    compute(0);
    __syncthreads();
    cp_wait<0>();
    __syncthreads();
    compute(1);
    __syncthreads();

    // epilogue: collapse k-even/odd, reduce 8 warp-partials via smem, tanh
    float* Rs = sm;  // [8][32][33] = 33792 B, aliases As (safe after sync)
#pragma unroll
    for (int i = 0; i < 4; i++) {
        int m = thrm + 8 * i;
#pragma unroll
        for (int j = 0; j < 8; j++) {
            int n = thrn + 4 * j;
            float lo, hi;
            unpack2(acc[i][j], lo, hi);
            Rs[(kg * 32 + m) * 33 + n] = lo + hi;
        }
    }
    __syncthreads();
#pragma unroll
    for (int u = 0; u < 4; u++) {
        int idx = t * 4 + u;
        int m = idx >> 5, n = idx & 31;
        float sum = 0.0f;
#pragma unroll
        for (int g = 0; g < 8; g++) sum += Rs[(g * 32 + m) * 33 + n];
        size_t o = (size_t)(m0 + m) * HID + (n0 + n);
        out[o] = tanhf(out[o] + sum);
    }
}

// ---------------- kernel 3: FC1 split-K partials ----------------
#define F1_BK 32
__global__ __launch_bounds__(256) void fc1_kernel(const float* __restrict__ W1) {
    __shared__ float Hs[BATCH][33];
    __shared__ float Ws[FC1N][33];
    int s = blockIdx.x;
    int t = threadIdx.x;
    const float* src = g_seq + (size_t)s * BATCH * HID;
    int tb = t & 63, tf = t >> 6;

    float acc0[25] = {}, acc1[25] = {};
    for (int k0 = 0; k0 < HID; k0 += F1_BK) {
#pragma unroll
        for (int q = 0; q < 4; q++) {
            int f4 = t + q * 256;
            int row = f4 >> 3, c4 = f4 & 7;
            float4 v = *(const float4*)(src + (size_t)row * HID + k0 + c4 * 4);
            Hs[row][c4 * 4 + 0] = v.x;
            Hs[row][c4 * 4 + 1] = v.y;
            Hs[row][c4 * 4 + 2] = v.z;
            Hs[row][c4 * 4 + 3] = v.w;
        }
        for (int f4 = t; f4 < FC1N * 8; f4 += 256) {
            int row = f4 >> 3, c4 = f4 & 7;
            float4 v = *(const float4*)(W1 + (size_t)row * (SEQ * HID) + (size_t)s * HID +
                                        k0 + c4 * 4);
            Ws[row][c4 * 4 + 0] = v.x;
            Ws[row][c4 * 4 + 1] = v.y;
            Ws[row][c4 * 4 + 2] = v.z;
            Ws[row][c4 * 4 + 3] = v.w;
        }
        __syncthreads();
#pragma unroll 2
        for (int k = 0; k < F1_BK; k++) {
            float a0 = Hs[2 * tb][k], a1 = Hs[2 * tb + 1][k];
#pragma unroll
            for (int j = 0; j < 25; j++) {
                float wv = Ws[tf * 25 + j][k];
                acc0[j] += a0 * wv;
                acc1[j] += a1 * wv;
            }
        }
        __syncthreads();
    }
    float* dst = g_part + (size_t)s * BATCH * FC1N;
#pragma unroll
    for (int j = 0; j < 25; j++) {
        dst[(size_t)(2 * tb) * FC1N + tf * 25 + j] = acc0[j];
        dst[(size_t)(2 * tb + 1) * FC1N + tf * 25 + j] = acc1[j];
    }
}

// ---------------- kernel 4: deterministic reduce + bias + relu ----------------
__global__ __launch_bounds__(256) void reduce_kernel(const float* __restrict__ b1) {
    int i = blockIdx.x * 256 + threadIdx.x;
    if (i >= BATCH * FC1N) return;
    int f = i % FC1N;
    float sum = b1[f];
    for (int s = 0; s < SEQ; s++) sum += g_part[(size_t)s * BATCH * FC1N + i];
    g_h1[i] = fmaxf(sum, 0.0f);
}

// ---------------- kernel 5: FC2 + log_softmax ----------------
__global__ __launch_bounds__(128) void fc2_kernel(const float* __restrict__ W2,
                                                  const float* __restrict__ b2,
                                                  float* __restrict__ out) {
    __shared__ float sW2[NCLS * FC1N];
    int t = threadIdx.x;
    for (int i = t; i < NCLS * FC1N; i += 128) sW2[i] = W2[i];
    __syncthreads();

    float hv[FC1N];
#pragma unroll
    for (int f = 0; f < FC1N; f++) hv[f] = g_h1[(size_t)t * FC1N + f];

    float logits[NCLS];
#pragma unroll
    for (int c = 0; c < NCLS; c++) {
        float acc = b2[c];
#pragma unroll
        for (int f = 0; f < FC1N; f++) acc += hv[f] * sW2[c * FC1N + f];
        logits[c] = acc;
    }
    float m = logits[0];
#pragma unroll
    for (int c = 1; c < NCLS; c++) m = fmaxf(m, logits[c]);
    float sum = 0.0f;
#pragma unroll
    for (int c = 0; c < NCLS; c++) sum += expf(logits[c] - m);
    float lse = m + logf(sum);
#pragma unroll
    for (int c = 0; c < NCLS; c++) out[(size_t)t * NCLS + c] = logits[c] - lse;
}

// ---------------- launch ----------------
extern "C" void kernel_launch(void* const* d_in, const int* in_sizes, int n_in,
                              void* d_out, int out_size) {
    const float* x = (const float*)d_in[0];
    const float* h0 = (const float*)d_in[1];
    const float* Wih = (const float*)d_in[2];
    const float* Whh = (const float*)d_in[3];
    const float* bih = (const float*)d_in[4];
    const float* bhh = (const float*)d_in[5];
    const float* W1 = (const float*)d_in[6];
    const float* b1 = (const float*)d_in[7];
    const float* W2 = (const float*)d_in[8];
    const float* b2 = (const float*)d_in[9];
    float* out = (float*)d_out;
    (void)in_sizes; (void)n_in; (void)out_size;

    cudaFuncSetAttribute(step_kernel, cudaFuncAttributeMaxDynamicSharedMemorySize,
                         ST_SMEM);

    xproj_kernel<<<dim3(HID / XP_BN, (SEQ * BATCH) / XP_BM), 256>>>(x, Wih, bih, bhh);
    for (int s = 0; s < SEQ; s++)
        step_kernel<<<dim3(32, 4), 256, ST_SMEM>>>(s, h0, Whh);
    fc1_kernel<<<SEQ, 256>>>(W1);
    reduce_kernel<<<(BATCH * FC1N + 255) / 256, 256>>>(b1);
    fc2_kernel<<<1, 128>>>(W2, b2, out);
}

// round 4
// speedup vs baseline: 2.1517x; 1.0587x over previous
#include <cuda_runtime.h>

#define FEAT 39
#define HID 1024
#define SEQ 254
#define NCLS 10
#define FC1N 100
#define BATCH 128

// Scratch (device globals; no allocation allowed).
__device__ float g_seq[SEQ * BATCH * HID];    // xproj then h_s, in place
__device__ float g_part[SEQ * BATCH * FC1N];  // FC1 split-K partials
__device__ float g_h1[BATCH * FC1N];

// ---------------- packed f32x2 + smem helpers ----------------
__device__ __forceinline__ unsigned smem_u32(const void* p) {
    return (unsigned)__cvta_generic_to_shared(p);
}
__device__ __forceinline__ void unpack2(unsigned long long v, float& lo, float& hi) {
    asm("mov.b64 {%0, %1}, %2;" : "=f"(lo), "=f"(hi) : "l"(v));
}
__device__ __forceinline__ void fma2(unsigned long long& d, unsigned long long a,
                                     unsigned long long b) {
    asm("fma.rn.f32x2 %0, %1, %2, %0;" : "+l"(d) : "l"(a), "l"(b));
}
__device__ __forceinline__ unsigned long long lds64(unsigned addr) {
    unsigned long long r;
    asm volatile("ld.shared.b64 %0, [%1];" : "=l"(r) : "r"(addr));
    return r;
}
__device__ __forceinline__ void cpasync16(unsigned dst, const void* src) {
    asm volatile("cp.async.cg.shared.global [%0], [%1], 16;" ::"r"(dst), "l"(src));
}
__device__ __forceinline__ void cp_commit() {
    asm volatile("cp.async.commit_group;");
}
template <int N>
__device__ __forceinline__ void cp_wait() {
    asm volatile("cp.async.wait_group %0;" ::"n"(N));
}

// ---------------- kernel 1: xproj = x @ W_ih^T + b_ih + b_hh, time-major ----------------
#define XP_BM 64
#define XP_BN 64
#define XP_PAD 41
__global__ __launch_bounds__(256) void xproj_kernel(
    const float* __restrict__ x, const float* __restrict__ Wih,
    const float* __restrict__ bih, const float* __restrict__ bhh) {
    __shared__ float Xs[XP_BM][XP_PAD];
    __shared__ float Ws[XP_BN][XP_PAD];
    int t = threadIdx.x;
    int n0 = blockIdx.x * XP_BN;
    int r0 = blockIdx.y * XP_BM;

    for (int i = t; i < XP_BM * FEAT; i += 256) {
        int row = i / FEAT, col = i % FEAT;
        int r = r0 + row;
        int b = r & (BATCH - 1), s = r >> 7;
        Xs[row][col] = x[((size_t)b * SEQ + s) * FEAT + col];
    }
    for (int i = t; i < XP_BN * FEAT; i += 256) {
        int row = i / FEAT, col = i % FEAT;
        Ws[row][col] = Wih[(size_t)(n0 + row) * FEAT + col];
    }
    __syncthreads();

    int tn = t & 15, tm = t >> 4;
    float acc[4][4] = {};
#pragma unroll
    for (int k = 0; k < FEAT; k++) {
        float a[4], w[4];
#pragma unroll
        for (int i = 0; i < 4; i++) a[i] = Xs[tm * 4 + i][k];
#pragma unroll
        for (int j = 0; j < 4; j++) w[j] = Ws[tn * 4 + j][k];
#pragma unroll
        for (int i = 0; i < 4; i++)
#pragma unroll
            for (int j = 0; j < 4; j++) acc[i][j] += a[i] * w[j];
    }
#pragma unroll
    for (int j = 0; j < 4; j++) {
        int n = n0 + tn * 4 + j;
        float bias = bih[n] + bhh[n];
#pragma unroll
        for (int i = 0; i < 4; i++) {
            int r = r0 + tm * 4 + i;
            g_seq[(size_t)r * HID + n] = acc[i][j] + bias;
        }
    }
}

// ---------------- kernel 2: recurrence step — warp-private pipeline ----------------
// out[m][n] = tanh(xp[m][n] + sum_k H[m][k]*Whh[n][k])
// 128 blocks (32 ngrp x 4 mgrp), 8 warps. Warp kg owns k-columns
// {kg*32 + 256*c : c=0..3}. Each warp stages its OWN 32x32 A and W tiles
// (3-deep cp.async ring) -> no __syncthreads in the mainloop; warps decouple
// and hide each other's latency. Accumulators packed over (k even, k odd).
#define AW_STRIDE 36                 // floats per tile row (16B aligned, bank-spread)
#define TILE_F (32 * AW_STRIDE)      // 1152 floats per tile
#define WARP_REGION (6 * TILE_F)     // 3 buffers x (A + W)
#define ST_SMEM (8 * WARP_REGION * 4)  // 221184 bytes

__global__ __launch_bounds__(256) void step_kernel(
    int s, const float* __restrict__ h0, const float* __restrict__ Whh) {
    extern __shared__ float sm[];
    const float* Hp = (s == 0) ? h0 : (g_seq + (size_t)(s - 1) * BATCH * HID);
    float* out = g_seq + (size_t)s * BATCH * HID;

    int t = threadIdx.x;
    int n0 = blockIdx.x * 32;
    int m0 = blockIdx.y * 32;
    int kg = t >> 5;
    int lane = t & 31;
    int thrm = lane >> 2;  // 0..7
    int thrn = lane & 3;   // 0..3

    unsigned smBase = smem_u32(sm);
    unsigned warpBase = smBase + (unsigned)(kg * WARP_REGION) * 4u;

    int srow0 = lane >> 3, sc4 = lane & 7;

    auto stage = [&](int c, int b) {
        unsigned dstA = warpBase + (unsigned)(b * 2 * TILE_F) * 4u;
        unsigned dstW = dstA + (unsigned)TILE_F * 4u;
        int koff = c * 256 + kg * 32 + sc4 * 4;
#pragma unroll
        for (int q = 0; q < 8; q++) {
            int row = srow0 + 4 * q;
            unsigned so = (unsigned)(row * AW_STRIDE + sc4 * 4) * 4u;
            cpasync16(dstA + so, Hp + (size_t)(m0 + row) * HID + koff);
            cpasync16(dstW + so, Whh + (size_t)(n0 + row) * HID + koff);
        }
        cp_commit();
    };

    unsigned long long acc[4][8];
#pragma unroll
    for (int i = 0; i < 4; i++)
#pragma unroll
        for (int j = 0; j < 8; j++) acc[i][j] = 0ull;

    unsigned aOff[4], wOff[8];
#pragma unroll
    for (int i = 0; i < 4; i++) aOff[i] = (unsigned)((thrm + 8 * i) * AW_STRIDE) * 4u;
#pragma unroll
    for (int j = 0; j < 8; j++) wOff[j] = (unsigned)((thrn + 4 * j) * AW_STRIDE) * 4u;

    auto compute = [&](int b) {
        unsigned aB = warpBase + (unsigned)(b * 2 * TILE_F) * 4u;
        unsigned wB = aB + (unsigned)TILE_F * 4u;
#pragma unroll
        for (int kp = 0; kp < 16; kp++) {
            unsigned kByte = (unsigned)kp * 8u;
            unsigned long long a[4], w[8];
#pragma unroll
            for (int i = 0; i < 4; i++) a[i] = lds64(aB + aOff[i] + kByte);
#pragma unroll
            for (int j = 0; j < 8; j++) w[j] = lds64(wB + wOff[j] + kByte);
#pragma unroll
            for (int i = 0; i < 4; i++)
#pragma unroll
                for (int j = 0; j < 8; j++) fma2(acc[i][j], a[i], w[j]);
        }
    };

    // warp-local 3-deep pipeline over 4 k-tiles; no block barriers
    stage(0, 0);
    stage(1, 1);
    stage(2, 2);
    cp_wait<2>();
    __syncwarp();
    compute(0);
    stage(3, 0);
    cp_wait<2>();
    __syncwarp();
    compute(1);
    cp_wait<1>();
    __syncwarp();
    compute(2);
    cp_wait<0>();
    __syncwarp();
    compute(0);

    __syncthreads();  // all warps done before reusing smem for reduction

    // epilogue: collapse k-even/odd, reduce 8 warp-partials, tanh
    float* Rs = sm;  // [8][32][33] floats = 33792 B (aliases tile buffers)
#pragma unroll
    for (int i = 0; i < 4; i++) {
        int m = thrm + 8 * i;
#pragma unroll
        for (int j = 0; j < 8; j++) {
            int n = thrn + 4 * j;
            float lo, hi;
            unpack2(acc[i][j], lo, hi);
            Rs[(kg * 32 + m) * 33 + n] = lo + hi;
        }
    }
    __syncthreads();
#pragma unroll
    for (int u = 0; u < 4; u++) {
        int idx = t * 4 + u;
        int m = idx >> 5, n = idx & 31;
        float sum = 0.0f;
#pragma unroll
        for (int g = 0; g < 8; g++) sum += Rs[(g * 32 + m) * 33 + n];
        size_t o = (size_t)(m0 + m) * HID + (n0 + n);
        out[o] = tanhf(out[o] + sum);
    }
}

// ---------------- kernel 3: FC1 split-K partials (fma2, batch-pair packed) ----------------
// g_part[s][b][f] = sum_k h_s[b][k] * W1[f][s*1024+k]
__global__ __launch_bounds__(256) void fc1_kernel(const float* __restrict__ W1) {
    __shared__ float Hs[32][130];   // transposed [k][b], 64-bit loads over b-pairs
    __shared__ float2 Wp[FC1N][34]; // duplicated {w,w} pairs for fma2
    int s = blockIdx.x;
    int t = threadIdx.x;
    const float* src = g_seq + (size_t)s * BATCH * HID;
    int tb = t & 63, tf = t >> 6;  // tb: batch-pair, tf: f-group of 25

    unsigned long long acc[25];
#pragma unroll
    for (int j = 0; j < 25; j++) acc[j] = 0ull;

    unsigned hBase = smem_u32(&Hs[0][0]) + (unsigned)(2 * tb) * 4u;
    unsigned wBase = smem_u32(&Wp[0][0]) + (unsigned)(tf * 25) * 34u * 8u;

    for (int k0 = 0; k0 < HID; k0 += 32) {
#pragma unroll
        for (int q = 0; q < 4; q++) {
            int f4 = t + q * 256;
            int row = f4 >> 3, c4 = f4 & 7;
            float4 v = *(const float4*)(src + (size_t)row * HID + k0 + c4 * 4);
            Hs[c4 * 4 + 0][row] = v.x;
            Hs[c4 * 4 + 1][row] = v.y;
            Hs[c4 * 4 + 2][row] = v.z;
            Hs[c4 * 4 + 3][row] = v.w;
        }
        for (int f4 = t; f4 < FC1N * 8; f4 += 256) {
            int row = f4 >> 3, c4 = f4 & 7;
            float4 v = *(const float4*)(W1 + (size_t)row * (SEQ * HID) + (size_t)s * HID +
                                        k0 + c4 * 4);
            Wp[row][c4 * 4 + 0] = make_float2(v.x, v.x);
            Wp[row][c4 * 4 + 1] = make_float2(v.y, v.y);
            Wp[row][c4 * 4 + 2] = make_float2(v.z, v.z);
            Wp[row][c4 * 4 + 3] = make_float2(v.w, v.w);
        }
        __syncthreads();
#pragma unroll 4
        for (int k = 0; k < 32; k++) {
            unsigned long long h2 = lds64(hBase + (unsigned)(k * 130) * 4u);
#pragma unroll
            for (int j = 0; j < 25; j++) {
                unsigned long long wv = lds64(wBase + (unsigned)(j * 34 + k) * 8u);
                fma2(acc[j], h2, wv);
            }
        }
        __syncthreads();
    }
    float* dst = g_part + (size_t)s * BATCH * FC1N;
#pragma unroll
    for (int j = 0; j < 25; j++) {
        float lo, hi;
        unpack2(acc[j], lo, hi);
        dst[(size_t)(2 * tb) * FC1N + tf * 25 + j] = lo;
        dst[(size_t)(2 * tb + 1) * FC1N + tf * 25 + j] = hi;
    }
}

// ---------------- kernel 4: deterministic reduce + bias + relu ----------------
__global__ __launch_bounds__(256) void reduce_kernel(const float* __restrict__ b1) {
    int i = blockIdx.x * 256 + threadIdx.x;
    if (i >= BATCH * FC1N) return;
    int f = i % FC1N;
    float p0 = 0.0f, p1 = 0.0f;
    for (int s = 0; s < SEQ; s += 2) {
        p0 += g_part[(size_t)s * BATCH * FC1N + i];
        p1 += g_part[(size_t)(s + 1) * BATCH * FC1N + i];
    }
    g_h1[i] = fmaxf(b1[f] + p0 + p1, 0.0f);
}

// ---------------- kernel 5: FC2 + log_softmax ----------------
__global__ __launch_bounds__(128) void fc2_kernel(const float* __restrict__ W2,
                                                  const float* __restrict__ b2,
                                                  float* __restrict__ out) {
    __shared__ float sW2[NCLS * FC1N];
    int t = threadIdx.x;
    for (int i = t; i < NCLS * FC1N; i += 128) sW2[i] = W2[i];
    __syncthreads();

    float hv[FC1N];
#pragma unroll
    for (int f = 0; f < FC1N; f++) hv[f] = g_h1[(size_t)t * FC1N + f];

    float logits[NCLS];
#pragma unroll
    for (int c = 0; c < NCLS; c++) {
        float acc = b2[c];
#pragma unroll
        for (int f = 0; f < FC1N; f++) acc += hv[f] * sW2[c * FC1N + f];
        logits[c] = acc;
    }
    float m = logits[0];
#pragma unroll
    for (int c = 1; c < NCLS; c++) m = fmaxf(m, logits[c]);
    float sum = 0.0f;
#pragma unroll
    for (int c = 0; c < NCLS; c++) sum += expf(logits[c] - m);
    float lse = m + logf(sum);
#pragma unroll
    for (int c = 0; c < NCLS; c++) out[(size_t)t * NCLS + c] = logits[c] - lse;
}

// ---------------- launch ----------------
extern "C" void kernel_launch(void* const* d_in, const int* in_sizes, int n_in,
                              void* d_out, int out_size) {
    const float* x = (const float*)d_in[0];
    const float* h0 = (const float*)d_in[1];
    const float* Wih = (const float*)d_in[2];
    const float* Whh = (const float*)d_in[3];
    const float* bih = (const float*)d_in[4];
    const float* bhh = (const float*)d_in[5];
    const float* W1 = (const float*)d_in[6];
    const float* b1 = (const float*)d_in[7];
    const float* W2 = (const float*)d_in[8];
    const float* b2 = (const float*)d_in[9];
    float* out = (float*)d_out;
    (void)in_sizes; (void)n_in; (void)out_size;

    cudaFuncSetAttribute(step_kernel, cudaFuncAttributeMaxDynamicSharedMemorySize,
                         ST_SMEM);

    xproj_kernel<<<dim3(HID / XP_BN, (SEQ * BATCH) / XP_BM), 256>>>(x, Wih, bih, bhh);
    for (int s = 0; s < SEQ; s++)
        step_kernel<<<dim3(32, 4), 256, ST_SMEM>>>(s, h0, Whh);
    fc1_kernel<<<SEQ, 256>>>(W1);
    reduce_kernel<<<(BATCH * FC1N + 255) / 256, 256>>>(b1);
    fc2_kernel<<<1, 128>>>(W2, b2, out);
}